// round 13
// baseline (speedup 1.0000x reference)
#include <cuda_runtime.h>
#include <cuda_fp16.h>
#include <math.h>
#include <stdint.h>

// ---------------- problem constants ----------------
#define T_TOK 2048      // BATCH*SEQ
#define HID   8192
#define QKVW  9216      // G*(HQ+2)*HEAD = 8*18*64
#define GKV   8
#define HQ    16
#define HEADD 64
#define SEQ   1024

typedef __half h16;

// ---------------- scratch (__device__ globals; allocation-free rule) ----------------
__device__ __align__(128) h16  g_ahi[(size_t)T_TOK * HID];
__device__ __align__(128) h16  g_alo[(size_t)T_TOK * HID];
__device__ __align__(128) h16  g_o[(size_t)T_TOK * HID];          // attention out (single fp16)
__device__ __align__(128) h16  g_wq_hi[(size_t)QKVW * HID];
__device__ __align__(128) h16  g_wq_lo[(size_t)QKVW * HID];
__device__ __align__(128) h16  g_wd_hi[(size_t)HID * HID];
// split QKV for tensor-core attention (V needs no lo: PV is 1-pass)
__device__ __align__(128) h16  g_qh[(size_t)T_TOK * GKV * HQ * HEADD];
__device__ __align__(128) h16  g_ql[(size_t)T_TOK * GKV * HQ * HEADD];
__device__ __align__(128) h16  g_kh[(size_t)T_TOK * GKV * HEADD];
__device__ __align__(128) h16  g_kl[(size_t)T_TOK * GKV * HEADD];
__device__ __align__(128) h16  g_vh[(size_t)T_TOK * GKV * HEADD];

// ---------------- side streams for fork-join overlap (static init: outside
// mem checkpoints; no device allocation at launch time) ----------------
struct SideStreams {
    cudaStream_t sd, ss;
    cudaEvent_t evFork, evWd, evSp;
    SideStreams() {
        cudaStreamCreateWithFlags(&sd, cudaStreamNonBlocking);
        cudaStreamCreateWithFlags(&ss, cudaStreamNonBlocking);
        cudaEventCreateWithFlags(&evFork, cudaEventDisableTiming);
        cudaEventCreateWithFlags(&evWd,   cudaEventDisableTiming);
        cudaEventCreateWithFlags(&evSp,   cudaEventDisableTiming);
    }
};
static SideStreams g_ss;

// ---------------- PTX helpers ----------------
__device__ __forceinline__ uint32_t smem_u32(const void* p) {
    uint32_t a;
    asm("{ .reg .u64 t; cvta.to.shared.u64 t, %1; cvt.u32.u64 %0, t; }" : "=r"(a) : "l"(p));
    return a;
}
#define CPA16(dst, src)   asm volatile("cp.async.cg.shared.global [%0], [%1], 16;" :: "r"(dst), "l"(src))
#define CPA_COMMIT()      asm volatile("cp.async.commit_group;" ::: "memory")
#define CPA_WAIT(n)       asm volatile("cp.async.wait_group %0;" :: "n"(n) : "memory")

__device__ __forceinline__ void ldmat_x4(uint32_t* r, uint32_t addr) {
    asm volatile("ldmatrix.sync.aligned.m8n8.x4.shared.b16 {%0,%1,%2,%3}, [%4];"
        : "=r"(r[0]), "=r"(r[1]), "=r"(r[2]), "=r"(r[3]) : "r"(addr));
}
__device__ __forceinline__ void ldmat_x4_t(uint32_t* r, uint32_t addr) {
    asm volatile("ldmatrix.sync.aligned.m8n8.x4.trans.shared.b16 {%0,%1,%2,%3}, [%4];"
        : "=r"(r[0]), "=r"(r[1]), "=r"(r[2]), "=r"(r[3]) : "r"(addr));
}
__device__ __forceinline__ void mma16816(float* d, const uint32_t* a, const uint32_t* b) {
    asm volatile("mma.sync.aligned.m16n8k16.row.col.f32.f16.f16.f32 "
        "{%0,%1,%2,%3}, {%4,%5,%6,%7}, {%8,%9}, {%0,%1,%2,%3};"
        : "+f"(d[0]), "+f"(d[1]), "+f"(d[2]), "+f"(d[3])
        : "r"(a[0]), "r"(a[1]), "r"(a[2]), "r"(a[3]), "r"(b[0]), "r"(b[1]));
}
#define SWZ(off)   ((off) ^ (((off) >> 3) & 0x70))   // 128B rows
#define SWZ64(off) ((off) ^ (((off) >> 3) & 0x30))   // 64B rows

__device__ __forceinline__ uint32_t gswz(uint32_t off, int rowb) {
    return (rowb == 64) ? SWZ64(off) : SWZ(off);
}

__device__ __forceinline__ uint32_t packh2(float a, float b) {
    __half2 t = __floats2half2_rn(a, b);
    return *(uint32_t*)&t;
}
__device__ __forceinline__ uint32_t residh2(uint32_t hp, float a, float b) {
    __half2 t = *(__half2*)&hp;
    return packh2(a - __half2float(t.x), b - __half2float(t.y));
}

// ---------------- fp32 -> (hi, lo) fp16 split ----------------
__global__ __launch_bounds__(256) void split_kernel(
    const float* __restrict__ x, h16* __restrict__ hi, h16* __restrict__ lo, int n4)
{
    int i = blockIdx.x * 256 + threadIdx.x;
    if (i >= n4) return;
    float4 v = *(const float4*)(x + (size_t)i * 4);
    __half2 h01 = __floats2half2_rn(v.x, v.y);
    __half2 h23 = __floats2half2_rn(v.z, v.w);
    __half2 l01 = __floats2half2_rn(v.x - __half2float(h01.x), v.y - __half2float(h01.y));
    __half2 l23 = __floats2half2_rn(v.z - __half2float(h23.x), v.w - __half2float(h23.y));
    *(__half2*)(hi + (size_t)i * 4)     = h01;
    *(__half2*)(hi + (size_t)i * 4 + 2) = h23;
    *(__half2*)(lo + (size_t)i * 4)     = l01;
    *(__half2*)(lo + (size_t)i * 4 + 2) = l23;
}

// ---------------- W [K,N] fp32 -> fp16 [N,K] (transpose + optional lo split) ----------------
__global__ __launch_bounds__(256) void transpose_split_kernel(
    const float* __restrict__ W, int K, int N, h16* __restrict__ oh, h16* __restrict__ ol)
{
    __shared__ float t[32][33];
    const int tx = threadIdx.x, ty = threadIdx.y;     // block (32, 8)
    const int k0 = blockIdx.y * 32, n0 = blockIdx.x * 32;
    #pragma unroll
    for (int j = ty; j < 32; j += 8)
        t[j][tx] = W[(size_t)(k0 + j) * N + n0 + tx];
    __syncthreads();
    #pragma unroll
    for (int j = ty; j < 32; j += 8) {
        float v = t[tx][j];
        h16 h = __float2half_rn(v);
        oh[(size_t)(n0 + j) * K + k0 + tx] = h;
        if (ol) {
            h16 l = __float2half_rn(v - __half2float(h));
            ol[(size_t)(n0 + j) * K + k0 + tx] = l;
        }
    }
}

// ---------------- split-fp16 GEMM via mma.sync ----------------
// CTA tile 128x128, 8 warps (4M x 2N), 3-stage cp.async, 2 CTAs/SM,
// one __syncthreads per chunk. K-chunk templated:
//   KCHUNK=32: 64B rows, SW64 (QKV 3-pass: stage 32 KB)
//   KCHUNK=64: 128B rows, SW128 (dense 1-pass: stage 32 KB)
// EPI==0: fp32 C.  EPI==1: fused RoPE + fp16 hi/lo split to q/k/v arrays.
#define NSTG 3

template<int PASSES, int EPI, int KCHUNK>
__global__ __launch_bounds__(256, 2) void gemm_mma(
    int M, int N, int K,
    const h16* __restrict__ A0, const h16* __restrict__ A1,
    const h16* __restrict__ B0, const h16* __restrict__ B1,
    float* __restrict__ C,
    const float* __restrict__ cosv, const float* __restrict__ sinv,
    h16* __restrict__ qh, h16* __restrict__ ql,
    h16* __restrict__ kh, h16* __restrict__ kl,
    h16* __restrict__ vh)
{
    constexpr int NTILE = (PASSES == 3) ? 4 : 2;
    constexpr int ROWB  = KCHUNK * 2;          // bytes per tile row
    constexpr int NKS   = KCHUNK / 16;         // k-steps per chunk
    constexpr int CPR   = ROWB / 16;           // 16B chunks per row
    constexpr uint32_t TB = 128u * ROWB;       // tile bytes
    constexpr uint32_t SB = NTILE * TB;        // stage bytes
    constexpr int CHT = NTILE * 128 * CPR / 256;  // per-thread cp.async per stage

    extern __shared__ char smem[];
    const uint32_t sb = smem_u32(smem);
    const int tid = threadIdx.x, wid = tid >> 5, lane = tid & 31;
    const int m0 = blockIdx.y * 128, n0 = blockIdx.x * 128;
    const int wm = wid & 3, wn = wid >> 2;

    const h16* srcs4[4] = { A0, A1, B0, B1 };
    const h16* srcs2[2] = { A0, B0 };
    const int rb4[4] = { m0, m0, n0, n0 };
    const int rb2[2] = { m0, n0 };

    float acc[2][8][4];
    #pragma unroll
    for (int i = 0; i < 2; i++)
        #pragma unroll
        for (int j = 0; j < 8; j++)
            #pragma unroll
            for (int q = 0; q < 4; q++) acc[i][j][q] = 0.f;

    const int nch = K / KCHUNK;

    #define ISSUE(c, st) do {                                                     \
        const uint32_t base_ = sb + (uint32_t)(st) * SB;                          \
        _Pragma("unroll")                                                         \
        for (int j_ = 0; j_ < CHT; ++j_) {                                        \
            const int i_ = tid + j_ * 256;                                        \
            const int t_ = i_ / (128 * CPR);                                      \
            const int rem_ = i_ - t_ * 128 * CPR;                                 \
            const int r_ = rem_ / CPR, ch_ = rem_ % CPR;                          \
            const uint32_t dst_ = base_ + t_ * TB + gswz((uint32_t)(r_ * ROWB + ch_ * 16), ROWB); \
            const h16* g_ = (PASSES == 3 ? srcs4[t_] : srcs2[t_])                 \
                + (size_t)((PASSES == 3 ? rb4[t_] : rb2[t_]) + r_) * K + (c) * KCHUNK + ch_ * 8; \
            CPA16(dst_, g_);                                                      \
        }                                                                         \
        CPA_COMMIT();                                                             \
    } while (0)

    ISSUE(0, 0);
    if (nch > 1) ISSUE(1, 1);

    const int arow = wm * 32 + (lane & 15);
    const int ahalf = lane >> 4;
    const int brow = wn * 64 + ((lane >> 4) << 3) + (lane & 7);
    const int bhalf = (lane >> 3) & 1;

    for (int c = 0; c < nch; ++c) {
        if (c + 1 < nch) { CPA_WAIT(1); } else { CPA_WAIT(0); }
        __syncthreads();
        if (c + 2 < nch) ISSUE(c + 2, (c + 2) % NSTG);

        const uint32_t base = sb + (uint32_t)(c % NSTG) * SB;
        const uint32_t abh = base;
        const uint32_t abl = base + TB;                           // PASSES==3 only
        const uint32_t bbh = base + ((PASSES == 3) ? 2 * TB : TB);
        const uint32_t bbl = bbh + TB;                            // PASSES==3 only

        #pragma unroll
        for (int ks = 0; ks < NKS; ++ks) {
            uint32_t ah[2][4], al[2][4], bh[4][4], bl[4][4];
            #pragma unroll
            for (int mt = 0; mt < 2; ++mt) {
                ldmat_x4(ah[mt], abh + gswz((uint32_t)((arow + mt * 16) * ROWB + (ks * 2 + ahalf) * 16), ROWB));
                if (PASSES == 3)
                    ldmat_x4(al[mt], abl + gswz((uint32_t)((arow + mt * 16) * ROWB + (ks * 2 + ahalf) * 16), ROWB));
            }
            #pragma unroll
            for (int n4 = 0; n4 < 4; ++n4) {
                ldmat_x4(bh[n4], bbh + gswz((uint32_t)((brow + n4 * 16) * ROWB + (ks * 2 + bhalf) * 16), ROWB));
                if (PASSES == 3)
                    ldmat_x4(bl[n4], bbl + gswz((uint32_t)((brow + n4 * 16) * ROWB + (ks * 2 + bhalf) * 16), ROWB));
            }
            #pragma unroll
            for (int mt = 0; mt < 2; ++mt)
                #pragma unroll
                for (int nt = 0; nt < 8; ++nt)
                    mma16816(acc[mt][nt], ah[mt], &bh[nt >> 1][(nt & 1) * 2]);
            if (PASSES == 3) {
                #pragma unroll
                for (int mt = 0; mt < 2; ++mt)
                    #pragma unroll
                    for (int nt = 0; nt < 8; ++nt)
                        mma16816(acc[mt][nt], ah[mt], &bl[nt >> 1][(nt & 1) * 2]);
                #pragma unroll
                for (int mt = 0; mt < 2; ++mt)
                    #pragma unroll
                    for (int nt = 0; nt < 8; ++nt)
                        mma16816(acc[mt][nt], al[mt], &bh[nt >> 1][(nt & 1) * 2]);
            }
        }
    }

    if (EPI == 0) {
        const int crow = m0 + wm * 32 + (lane >> 2);
        const int ccol = n0 + wn * 64 + (lane & 3) * 2;
        #pragma unroll
        for (int mt = 0; mt < 2; ++mt) {
            #pragma unroll
            for (int nt = 0; nt < 8; ++nt) {
                float* p0 = C + (size_t)(crow + mt * 16) * N + ccol + nt * 8;
                float* p1 = p0 + 8 * (size_t)N;
                *(float2*)p0 = make_float2(acc[mt][nt][0], acc[mt][nt][1]);
                *(float2*)p1 = make_float2(acc[mt][nt][2], acc[mt][nt][3]);
            }
        }
    } else {
        // fused RoPE + fp16 hi/lo split. Warp tile = exactly one 64-dim head.
        const int hh = (n0 + wn * 64) >> 6;        // global head index 0..143
        const int g  = hh / 18, hd = hh % 18;
        const int crow = m0 + wm * 32 + (lane >> 2);
        const int d0base = (lane & 3) * 2;
        #pragma unroll
        for (int mt = 0; mt < 2; ++mt) {
            #pragma unroll
            for (int half = 0; half < 2; ++half) {
                const int r = crow + mt * 16 + half * 8;   // global token
                #pragma unroll
                for (int nt = 0; nt < 4; ++nt) {
                    const int d = d0base + nt * 8;          // 0..30 even
                    float x1a = acc[mt][nt][half * 2],     x1b = acc[mt][nt][half * 2 + 1];
                    float x2a = acc[mt][nt + 4][half * 2], x2b = acc[mt][nt + 4][half * 2 + 1];
                    float y1a, y1b, y2a, y2b;
                    if (hd < 17) {   // rope on q heads and k
                        float ca = cosv[r * 32 + d],  cb = cosv[r * 32 + d + 1];
                        float sa = sinv[r * 32 + d],  sb2 = sinv[r * 32 + d + 1];
                        y1a = x1a * ca - x2a * sa;  y2a = x2a * ca + x1a * sa;
                        y1b = x1b * cb - x2b * sb2; y2b = x2b * cb + x1b * sb2;
                    } else { y1a = x1a; y1b = x1b; y2a = x2a; y2b = x2b; }

                    uint32_t h1 = packh2(y1a, y1b);
                    uint32_t h2 = packh2(y2a, y2b);

                    if (hd < HQ) {
                        size_t off = (((size_t)r * GKV + g) * HQ + hd) * HEADD;
                        *(uint32_t*)(qh + off + d)      = h1;
                        *(uint32_t*)(ql + off + d)      = residh2(h1, y1a, y1b);
                        *(uint32_t*)(qh + off + d + 32) = h2;
                        *(uint32_t*)(ql + off + d + 32) = residh2(h2, y2a, y2b);
                    } else if (hd == HQ) {
                        size_t off = ((size_t)r * GKV + g) * HEADD;
                        *(uint32_t*)(kh + off + d)      = h1;
                        *(uint32_t*)(kl + off + d)      = residh2(h1, y1a, y1b);
                        *(uint32_t*)(kh + off + d + 32) = h2;
                        *(uint32_t*)(kl + off + d + 32) = residh2(h2, y2a, y2b);
                    } else {   // V: single fp16 only (PV is 1-pass)
                        size_t off = ((size_t)r * GKV + g) * HEADD;
                        *(uint32_t*)(vh + off + d)      = h1;
                        *(uint32_t*)(vh + off + d + 32) = h2;
                    }
                }
            }
        }
    }
    #undef ISSUE
}

// ---------------- HMMA flash attention ----------------
// QK^T: 3-pass split fp16 (precision-critical: logits). PV: 1-pass.
// KV stage = {Kh 8K | Kl 8K | Vh 8K} = 24 KB, 2 stages.
#define BQ 128
#define BKV 64
#define QSMB 32768
#define KVST 24576
#define ATT_SMEM (QSMB + 2 * KVST)

__global__ __launch_bounds__(256) void attn_mma_kernel(
    const h16* __restrict__ qh, const h16* __restrict__ ql,
    const h16* __restrict__ kh, const h16* __restrict__ kl,
    const h16* __restrict__ vh,
    h16* __restrict__ outo)
{
    extern __shared__ char smem[];
    const uint32_t sb = smem_u32(smem);
    const int qb = blockIdx.x;
    const int h  = blockIdx.y;
    const int bg = blockIdx.z;
    const int b  = bg >> 3, g = bg & 7;
    const int tid = threadIdx.x, wid = tid >> 5, lane = tid & 31;
    const int tb = b * SEQ, q0 = qb * BQ;

    const h16* kvsrc[3] = { kh, kl, vh };

    #pragma unroll
    for (int arr = 0; arr < 2; ++arr) {
        const h16* src = arr ? ql : qh;
        #pragma unroll
        for (int j = 0; j < 4; ++j) {
            const int i = tid + j * 256;
            const int r = i >> 3, ch = i & 7;
            const uint32_t dst = sb + arr * 16384 + SWZ((uint32_t)(r * 128 + ch * 16));
            const h16* gp = src + (((size_t)(tb + q0 + r) * GKV + g) * HQ + h) * HEADD + ch * 8;
            CPA16(dst, gp);
        }
    }
    CPA_COMMIT();

    #define ISSUE_KV(jb_, st_) do {                                                   \
        const int j0_ = (jb_) * BKV;                                                  \
        const uint32_t base_ = sb + QSMB + (st_) * KVST;                              \
        _Pragma("unroll")                                                             \
        for (int q_ = 0; q_ < 6; ++q_) {                                              \
            const int i_ = tid + q_ * 256;                                            \
            const int arr_ = i_ >> 9, r_ = (i_ >> 3) & 63, ch_ = i_ & 7;              \
            const h16* gp_ = kvsrc[arr_] + ((size_t)(tb + j0_ + r_) * GKV + g) * HEADD + ch_ * 8; \
            CPA16(base_ + arr_ * 8192 + SWZ((uint32_t)(r_ * 128 + ch_ * 16)), gp_);   \
        }                                                                             \
        CPA_COMMIT();                                                                 \
    } while (0)

    ISSUE_KV(0, 0);
    CPA_WAIT(1);
    __syncthreads();

    uint32_t aqh[4][4], aql[4][4];
    const int arow = wid * 16 + (lane & 15);
    const int ahalf = lane >> 4;
    #pragma unroll
    for (int ks = 0; ks < 4; ++ks) {
        ldmat_x4(aqh[ks], sb + SWZ((uint32_t)(arow * 128 + (ks * 2 + ahalf) * 16)));
        ldmat_x4(aql[ks], sb + 16384 + SWZ((uint32_t)(arow * 128 + (ks * 2 + ahalf) * 16)));
    }

    float acc[8][4];
    #pragma unroll
    for (int i = 0; i < 8; i++)
        #pragma unroll
        for (int q = 0; q < 4; q++) acc[i][q] = 0.f;
    float m0 = -1e30f, m1 = -1e30f, l0 = 0.f, l1 = 0.f;

    const int brow = ((lane >> 4) << 3) + (lane & 7);
    const int bhalf = (lane >> 3) & 1;
    const int jmax = 2 * qb + 1;

    for (int jb = 0; jb <= jmax; ++jb) {
        const int st = jb & 1;
        if (jb < jmax) { ISSUE_KV(jb + 1, (jb + 1) & 1); CPA_WAIT(1); }
        else           { CPA_WAIT(0); }
        __syncthreads();

        const uint32_t kbh = sb + QSMB + st * KVST;
        const uint32_t kbl = kbh + 8192;
        const uint32_t vbh = kbh + 16384;

        float s[8][4];
        #pragma unroll
        for (int i = 0; i < 8; i++)
            #pragma unroll
            for (int q = 0; q < 4; q++) s[i][q] = 0.f;

        #pragma unroll
        for (int ks = 0; ks < 4; ++ks) {
            #pragma unroll
            for (int g4 = 0; g4 < 4; ++g4) {
                uint32_t bb[4];
                ldmat_x4(bb, kbh + SWZ((uint32_t)((g4 * 16 + brow) * 128 + (ks * 2 + bhalf) * 16)));
                mma16816(s[2 * g4],     aqh[ks], &bb[0]);
                mma16816(s[2 * g4 + 1], aqh[ks], &bb[2]);
                mma16816(s[2 * g4],     aql[ks], &bb[0]);
                mma16816(s[2 * g4 + 1], aql[ks], &bb[2]);
                ldmat_x4(bb, kbl + SWZ((uint32_t)((g4 * 16 + brow) * 128 + (ks * 2 + bhalf) * 16)));
                mma16816(s[2 * g4],     aqh[ks], &bb[0]);
                mma16816(s[2 * g4 + 1], aqh[ks], &bb[2]);
            }
        }

        const float SCALE = 0.125f;
        const int j0 = jb * BKV;
        const int r0g = q0 + wid * 16 + (lane >> 2);
        if (jb >= 2 * qb) {
            #pragma unroll
            for (int nt = 0; nt < 8; ++nt) {
                const int kc = j0 + nt * 8 + (lane & 3) * 2;
                #pragma unroll
                for (int q = 0; q < 4; ++q) {
                    const int row = r0g + ((q >> 1) << 3);
                    const int key = kc + (q & 1);
                    s[nt][q] = (key <= row) ? s[nt][q] * SCALE : -1e30f;
                }
            }
        } else {
            #pragma unroll
            for (int nt = 0; nt < 8; ++nt)
                #pragma unroll
                for (int q = 0; q < 4; ++q) s[nt][q] *= SCALE;
        }

        float rm0 = -1e30f, rm1 = -1e30f;
        #pragma unroll
        for (int nt = 0; nt < 8; ++nt) {
            rm0 = fmaxf(rm0, fmaxf(s[nt][0], s[nt][1]));
            rm1 = fmaxf(rm1, fmaxf(s[nt][2], s[nt][3]));
        }
        rm0 = fmaxf(rm0, __shfl_xor_sync(0xffffffffu, rm0, 1));
        rm0 = fmaxf(rm0, __shfl_xor_sync(0xffffffffu, rm0, 2));
        rm1 = fmaxf(rm1, __shfl_xor_sync(0xffffffffu, rm1, 1));
        rm1 = fmaxf(rm1, __shfl_xor_sync(0xffffffffu, rm1, 2));

        const float nm0 = fmaxf(m0, rm0), nm1 = fmaxf(m1, rm1);
        const float c0 = __expf(m0 - nm0), c1 = __expf(m1 - nm1);
        float rs0 = 0.f, rs1 = 0.f;
        #pragma unroll
        for (int nt = 0; nt < 8; ++nt) {
            s[nt][0] = __expf(s[nt][0] - nm0);
            s[nt][1] = __expf(s[nt][1] - nm0);
            s[nt][2] = __expf(s[nt][2] - nm1);
            s[nt][3] = __expf(s[nt][3] - nm1);
            rs0 += s[nt][0] + s[nt][1];
            rs1 += s[nt][2] + s[nt][3];
        }
        rs0 += __shfl_xor_sync(0xffffffffu, rs0, 1);
        rs0 += __shfl_xor_sync(0xffffffffu, rs0, 2);
        rs1 += __shfl_xor_sync(0xffffffffu, rs1, 1);
        rs1 += __shfl_xor_sync(0xffffffffu, rs1, 2);
        l0 = l0 * c0 + rs0; l1 = l1 * c1 + rs1;
        m0 = nm0; m1 = nm1;
        #pragma unroll
        for (int nt = 0; nt < 8; ++nt) {
            acc[nt][0] *= c0; acc[nt][1] *= c0;
            acc[nt][2] *= c1; acc[nt][3] *= c1;
        }

        // P fragments: hi only (PV 1-pass)
        uint32_t ph[4][4];
        #pragma unroll
        for (int ks = 0; ks < 4; ++ks) {
            ph[ks][0] = packh2(s[2 * ks][0], s[2 * ks][1]);
            ph[ks][1] = packh2(s[2 * ks][2], s[2 * ks][3]);
            ph[ks][2] = packh2(s[2 * ks + 1][0], s[2 * ks + 1][1]);
            ph[ks][3] = packh2(s[2 * ks + 1][2], s[2 * ks + 1][3]);
        }

        const int vrow0 = ((lane >> 3) & 1) * 8 + (lane & 7);
        const int vch   = lane >> 4;
        #pragma unroll
        for (int ks = 0; ks < 4; ++ks) {
            #pragma unroll
            for (int g4 = 0; g4 < 4; ++g4) {
                uint32_t vv[4];
                ldmat_x4_t(vv, vbh + SWZ((uint32_t)((ks * 16 + vrow0) * 128 + (g4 * 2 + vch) * 16)));
                mma16816(acc[2 * g4],     ph[ks], &vv[0]);
                mma16816(acc[2 * g4 + 1], ph[ks], &vv[2]);
            }
        }
        __syncthreads();
    }
    #undef ISSUE_KV

    const float inv0 = 1.f / l0, inv1 = 1.f / l1;
    const int rA = q0 + wid * 16 + (lane >> 2);
    const size_t colbase = (size_t)(g * HQ + h) * HEADD + (lane & 3) * 2;
    #pragma unroll
    for (int half = 0; half < 2; ++half) {
        const int row = rA + half * 8;
        const float inv = half ? inv1 : inv0;
        const size_t base = (size_t)(tb + row) * HID + colbase;
        #pragma unroll
        for (int nt = 0; nt < 8; ++nt) {
            float v0 = acc[nt][half * 2] * inv;
            float v1 = acc[nt][half * 2 + 1] * inv;
            *(__half2*)(outo + base + nt * 8) = __floats2half2_rn(v0, v1);
        }
    }
}

// ---------------- launcher ----------------
extern "C" void kernel_launch(void* const* d_in, const int* in_sizes, int n_in,
                              void* d_out, int out_size)
{
    const float* hidden = (const float*)d_in[0];
    const float* cosv   = (const float*)d_in[1];
    const float* sinv   = (const float*)d_in[2];
    const float* Wqkv   = (const float*)d_in[3];
    const float* Wdense = (const float*)d_in[4];
    float* out = (float*)d_out;

    h16 *ahi, *alo, *oatt, *wqh, *wql, *wdh;
    h16 *qh, *ql, *kh, *kl, *vh;
    cudaGetSymbolAddress((void**)&ahi, g_ahi);
    cudaGetSymbolAddress((void**)&alo, g_alo);
    cudaGetSymbolAddress((void**)&oatt, g_o);
    cudaGetSymbolAddress((void**)&wqh, g_wq_hi);
    cudaGetSymbolAddress((void**)&wql, g_wq_lo);
    cudaGetSymbolAddress((void**)&wdh, g_wd_hi);
    cudaGetSymbolAddress((void**)&qh, g_qh);
    cudaGetSymbolAddress((void**)&ql, g_ql);
    cudaGetSymbolAddress((void**)&kh, g_kh);
    cudaGetSymbolAddress((void**)&kl, g_kl);
    cudaGetSymbolAddress((void**)&vh, g_vh);

    const int smem3 = NSTG * 4 * (128 * 64);    // 98304  (QKV: KC=32, 3-pass)
    const int smem1 = NSTG * 2 * (128 * 128);   // 98304  (dense: KC=64, 1-pass)
    cudaFuncSetAttribute(gemm_mma<3, 1, 32>, cudaFuncAttributeMaxDynamicSharedMemorySize, smem3);
    cudaFuncSetAttribute(gemm_mma<1, 0, 64>, cudaFuncAttributeMaxDynamicSharedMemorySize, smem1);
    cudaFuncSetAttribute(attn_mma_kernel, cudaFuncAttributeMaxDynamicSharedMemorySize, ATT_SMEM);

    // ---- fork: independent conversions onto side streams ----
    cudaEventRecord(g_ss.evFork, 0);

    // side stream sd: Wdense transpose (needed only by the last GEMM)
    cudaStreamWaitEvent(g_ss.sd, g_ss.evFork, 0);
    transpose_split_kernel<<<dim3(HID / 32, HID / 32), dim3(32, 8), 0, g_ss.sd>>>(
        Wdense, HID, HID, wdh, nullptr);
    cudaEventRecord(g_ss.evWd, g_ss.sd);

    // side stream ss: activation split (needed by QKV GEMM)
    cudaStreamWaitEvent(g_ss.ss, g_ss.evFork, 0);
    split_kernel<<<(T_TOK * HID / 4 + 255) / 256, 256, 0, g_ss.ss>>>(
        hidden, ahi, alo, T_TOK * HID / 4);
    cudaEventRecord(g_ss.evSp, g_ss.ss);

    // main: Wqkv transpose (needed by QKV GEMM)
    transpose_split_kernel<<<dim3(QKVW / 32, HID / 32), dim3(32, 8)>>>(Wqkv, HID, QKVW, wqh, wql);

    // join split before QKV GEMM
    cudaStreamWaitEvent(0, g_ss.evSp, 0);

    // 1) QKV projection: 3-pass split fp16 with fused RoPE + split epilogue
    gemm_mma<3, 1, 32><<<dim3(QKVW / 128, T_TOK / 128), 256, smem3>>>(
        T_TOK, QKVW, HID, ahi, alo, wqh, wql, nullptr,
        cosv, sinv, qh, ql, kh, kl, vh);

    // 2) HMMA causal GQA flash attention (QK 3-pass, PV 1-pass) -> single fp16
    attn_mma_kernel<<<dim3(SEQ / BQ, HQ, 16), 256, ATT_SMEM>>>(
        qh, ql, kh, kl, vh, oatt);

    // join Wdense transpose before dense GEMM
    cudaStreamWaitEvent(0, g_ss.evWd, 0);

    // 3) dense projection: single x single fp16, KC=64 (fewer barriers)
    gemm_mma<1, 0, 64><<<dim3(HID / 128, T_TOK / 128), 256, smem1>>>(
        T_TOK, HID, HID, oatt, nullptr, wdh, nullptr, out,
        nullptr, nullptr, nullptr, nullptr, nullptr, nullptr, nullptr);
}

// round 14
// speedup vs baseline: 1.5264x; 1.5264x over previous
#include <cuda_runtime.h>
#include <cuda_fp16.h>
#include <math.h>
#include <stdint.h>

// ---------------- problem constants ----------------
#define T_TOK 2048      // BATCH*SEQ
#define HID   8192
#define QKVW  9216      // G*(HQ+2)*HEAD = 8*18*64
#define GKV   8
#define HQ    16
#define HEADD 64
#define SEQ   1024

typedef __half h16;

// ---------------- scratch (__device__ globals; allocation-free rule) ----------------
__device__ __align__(128) h16  g_ahi[(size_t)T_TOK * HID];
__device__ __align__(128) h16  g_alo[(size_t)T_TOK * HID];
__device__ __align__(128) h16  g_o[(size_t)T_TOK * HID];          // attention out (single fp16)
__device__ __align__(128) h16  g_wq_hi[(size_t)QKVW * HID];
__device__ __align__(128) h16  g_wq_lo[(size_t)QKVW * HID];
__device__ __align__(128) h16  g_wd_hi[(size_t)HID * HID];
// split QKV for tensor-core attention (V needs no lo: PV is 1-pass)
__device__ __align__(128) h16  g_qh[(size_t)T_TOK * GKV * HQ * HEADD];
__device__ __align__(128) h16  g_ql[(size_t)T_TOK * GKV * HQ * HEADD];
__device__ __align__(128) h16  g_kh[(size_t)T_TOK * GKV * HEADD];
__device__ __align__(128) h16  g_kl[(size_t)T_TOK * GKV * HEADD];
__device__ __align__(128) h16  g_vh[(size_t)T_TOK * GKV * HEADD];

// ---------------- PTX helpers ----------------
__device__ __forceinline__ uint32_t smem_u32(const void* p) {
    uint32_t a;
    asm("{ .reg .u64 t; cvta.to.shared.u64 t, %1; cvt.u32.u64 %0, t; }" : "=r"(a) : "l"(p));
    return a;
}
#define CPA16(dst, src)   asm volatile("cp.async.cg.shared.global [%0], [%1], 16;" :: "r"(dst), "l"(src))
#define CPA_COMMIT()      asm volatile("cp.async.commit_group;" ::: "memory")
#define CPA_WAIT(n)       asm volatile("cp.async.wait_group %0;" :: "n"(n) : "memory")

__device__ __forceinline__ void ldmat_x4(uint32_t* r, uint32_t addr) {
    asm volatile("ldmatrix.sync.aligned.m8n8.x4.shared.b16 {%0,%1,%2,%3}, [%4];"
        : "=r"(r[0]), "=r"(r[1]), "=r"(r[2]), "=r"(r[3]) : "r"(addr));
}
__device__ __forceinline__ void ldmat_x4_t(uint32_t* r, uint32_t addr) {
    asm volatile("ldmatrix.sync.aligned.m8n8.x4.trans.shared.b16 {%0,%1,%2,%3}, [%4];"
        : "=r"(r[0]), "=r"(r[1]), "=r"(r[2]), "=r"(r[3]) : "r"(addr));
}
__device__ __forceinline__ void mma16816(float* d, const uint32_t* a, const uint32_t* b) {
    asm volatile("mma.sync.aligned.m16n8k16.row.col.f32.f16.f16.f32 "
        "{%0,%1,%2,%3}, {%4,%5,%6,%7}, {%8,%9}, {%0,%1,%2,%3};"
        : "+f"(d[0]), "+f"(d[1]), "+f"(d[2]), "+f"(d[3])
        : "r"(a[0]), "r"(a[1]), "r"(a[2]), "r"(a[3]), "r"(b[0]), "r"(b[1]));
}
#define SWZ(off)   ((off) ^ (((off) >> 3) & 0x70))   // 128B rows
#define SWZ64(off) ((off) ^ (((off) >> 3) & 0x30))   // 64B rows

__device__ __forceinline__ uint32_t gswz(uint32_t off, int rowb) {
    return (rowb == 64) ? SWZ64(off) : SWZ(off);
}

__device__ __forceinline__ uint32_t packh2(float a, float b) {
    __half2 t = __floats2half2_rn(a, b);
    return *(uint32_t*)&t;
}
__device__ __forceinline__ uint32_t residh2(uint32_t hp, float a, float b) {
    __half2 t = *(__half2*)&hp;
    return packh2(a - __half2float(t.x), b - __half2float(t.y));
}

// ---------------- fp32 -> (hi, lo) fp16 split ----------------
__global__ __launch_bounds__(256) void split_kernel(
    const float* __restrict__ x, h16* __restrict__ hi, h16* __restrict__ lo, int n4)
{
    int i = blockIdx.x * 256 + threadIdx.x;
    if (i >= n4) return;
    float4 v = *(const float4*)(x + (size_t)i * 4);
    __half2 h01 = __floats2half2_rn(v.x, v.y);
    __half2 h23 = __floats2half2_rn(v.z, v.w);
    __half2 l01 = __floats2half2_rn(v.x - __half2float(h01.x), v.y - __half2float(h01.y));
    __half2 l23 = __floats2half2_rn(v.z - __half2float(h23.x), v.w - __half2float(h23.y));
    *(__half2*)(hi + (size_t)i * 4)     = h01;
    *(__half2*)(hi + (size_t)i * 4 + 2) = h23;
    *(__half2*)(lo + (size_t)i * 4)     = l01;
    *(__half2*)(lo + (size_t)i * 4 + 2) = l23;
}

// ---------------- W [K,N] fp32 -> fp16 [N,K] (transpose + optional lo split) ----------------
__global__ __launch_bounds__(256) void transpose_split_kernel(
    const float* __restrict__ W, int K, int N, h16* __restrict__ oh, h16* __restrict__ ol)
{
    __shared__ float t[32][33];
    const int tx = threadIdx.x, ty = threadIdx.y;     // block (32, 8)
    const int k0 = blockIdx.y * 32, n0 = blockIdx.x * 32;
    #pragma unroll
    for (int j = ty; j < 32; j += 8)
        t[j][tx] = W[(size_t)(k0 + j) * N + n0 + tx];
    __syncthreads();
    #pragma unroll
    for (int j = ty; j < 32; j += 8) {
        float v = t[tx][j];
        h16 h = __float2half_rn(v);
        oh[(size_t)(n0 + j) * K + k0 + tx] = h;
        if (ol) {
            h16 l = __float2half_rn(v - __half2float(h));
            ol[(size_t)(n0 + j) * K + k0 + tx] = l;
        }
    }
}

// ---------------- split-fp16 GEMM via mma.sync ----------------
// CTA tile 128x128, 8 warps (4M x 2N), 3-stage cp.async, 2 CTAs/SM,
// one __syncthreads per chunk. K-chunk templated:
//   KCHUNK=32: 64B rows, SW64 (QKV 3-pass: stage 32 KB)
//   KCHUNK=64: 128B rows, SW128 (dense 1-pass: stage 32 KB)
// EPI==0: fp32 C.  EPI==1: fused RoPE + fp16 hi/lo split to q/k/v arrays.
#define NSTG 3

template<int PASSES, int EPI, int KCHUNK>
__global__ __launch_bounds__(256, 2) void gemm_mma(
    int M, int N, int K,
    const h16* __restrict__ A0, const h16* __restrict__ A1,
    const h16* __restrict__ B0, const h16* __restrict__ B1,
    float* __restrict__ C,
    const float* __restrict__ cosv, const float* __restrict__ sinv,
    h16* __restrict__ qh, h16* __restrict__ ql,
    h16* __restrict__ kh, h16* __restrict__ kl,
    h16* __restrict__ vh)
{
    constexpr int NTILE = (PASSES == 3) ? 4 : 2;
    constexpr int ROWB  = KCHUNK * 2;          // bytes per tile row
    constexpr int NKS   = KCHUNK / 16;         // k-steps per chunk
    constexpr int CPR   = ROWB / 16;           // 16B chunks per row
    constexpr uint32_t TB = 128u * ROWB;       // tile bytes
    constexpr uint32_t SB = NTILE * TB;        // stage bytes
    constexpr int CHT = NTILE * 128 * CPR / 256;  // per-thread cp.async per stage

    extern __shared__ char smem[];
    const uint32_t sb = smem_u32(smem);
    const int tid = threadIdx.x, wid = tid >> 5, lane = tid & 31;
    const int m0 = blockIdx.y * 128, n0 = blockIdx.x * 128;
    const int wm = wid & 3, wn = wid >> 2;

    const h16* srcs4[4] = { A0, A1, B0, B1 };
    const h16* srcs2[2] = { A0, B0 };
    const int rb4[4] = { m0, m0, n0, n0 };
    const int rb2[2] = { m0, n0 };

    float acc[2][8][4];
    #pragma unroll
    for (int i = 0; i < 2; i++)
        #pragma unroll
        for (int j = 0; j < 8; j++)
            #pragma unroll
            for (int q = 0; q < 4; q++) acc[i][j][q] = 0.f;

    const int nch = K / KCHUNK;

    #define ISSUE(c, st) do {                                                     \
        const uint32_t base_ = sb + (uint32_t)(st) * SB;                          \
        _Pragma("unroll")                                                         \
        for (int j_ = 0; j_ < CHT; ++j_) {                                        \
            const int i_ = tid + j_ * 256;                                        \
            const int t_ = i_ / (128 * CPR);                                      \
            const int rem_ = i_ - t_ * 128 * CPR;                                 \
            const int r_ = rem_ / CPR, ch_ = rem_ % CPR;                          \
            const uint32_t dst_ = base_ + t_ * TB + gswz((uint32_t)(r_ * ROWB + ch_ * 16), ROWB); \
            const h16* g_ = (PASSES == 3 ? srcs4[t_] : srcs2[t_])                 \
                + (size_t)((PASSES == 3 ? rb4[t_] : rb2[t_]) + r_) * K + (c) * KCHUNK + ch_ * 8; \
            CPA16(dst_, g_);                                                      \
        }                                                                         \
        CPA_COMMIT();                                                             \
    } while (0)

    ISSUE(0, 0);
    if (nch > 1) ISSUE(1, 1);

    const int arow = wm * 32 + (lane & 15);
    const int ahalf = lane >> 4;
    const int brow = wn * 64 + ((lane >> 4) << 3) + (lane & 7);
    const int bhalf = (lane >> 3) & 1;

    for (int c = 0; c < nch; ++c) {
        if (c + 1 < nch) { CPA_WAIT(1); } else { CPA_WAIT(0); }
        __syncthreads();
        if (c + 2 < nch) ISSUE(c + 2, (c + 2) % NSTG);

        const uint32_t base = sb + (uint32_t)(c % NSTG) * SB;
        const uint32_t abh = base;
        const uint32_t abl = base + TB;                           // PASSES==3 only
        const uint32_t bbh = base + ((PASSES == 3) ? 2 * TB : TB);
        const uint32_t bbl = bbh + TB;                            // PASSES==3 only

        #pragma unroll
        for (int ks = 0; ks < NKS; ++ks) {
            uint32_t ah[2][4], al[2][4], bh[4][4], bl[4][4];
            #pragma unroll
            for (int mt = 0; mt < 2; ++mt) {
                ldmat_x4(ah[mt], abh + gswz((uint32_t)((arow + mt * 16) * ROWB + (ks * 2 + ahalf) * 16), ROWB));
                if (PASSES == 3)
                    ldmat_x4(al[mt], abl + gswz((uint32_t)((arow + mt * 16) * ROWB + (ks * 2 + ahalf) * 16), ROWB));
            }
            #pragma unroll
            for (int n4 = 0; n4 < 4; ++n4) {
                ldmat_x4(bh[n4], bbh + gswz((uint32_t)((brow + n4 * 16) * ROWB + (ks * 2 + bhalf) * 16), ROWB));
                if (PASSES == 3)
                    ldmat_x4(bl[n4], bbl + gswz((uint32_t)((brow + n4 * 16) * ROWB + (ks * 2 + bhalf) * 16), ROWB));
            }
            #pragma unroll
            for (int mt = 0; mt < 2; ++mt)
                #pragma unroll
                for (int nt = 0; nt < 8; ++nt)
                    mma16816(acc[mt][nt], ah[mt], &bh[nt >> 1][(nt & 1) * 2]);
            if (PASSES == 3) {
                #pragma unroll
                for (int mt = 0; mt < 2; ++mt)
                    #pragma unroll
                    for (int nt = 0; nt < 8; ++nt)
                        mma16816(acc[mt][nt], ah[mt], &bl[nt >> 1][(nt & 1) * 2]);
                #pragma unroll
                for (int mt = 0; mt < 2; ++mt)
                    #pragma unroll
                    for (int nt = 0; nt < 8; ++nt)
                        mma16816(acc[mt][nt], al[mt], &bh[nt >> 1][(nt & 1) * 2]);
            }
        }
    }

    if (EPI == 0) {
        const int crow = m0 + wm * 32 + (lane >> 2);
        const int ccol = n0 + wn * 64 + (lane & 3) * 2;
        #pragma unroll
        for (int mt = 0; mt < 2; ++mt) {
            #pragma unroll
            for (int nt = 0; nt < 8; ++nt) {
                float* p0 = C + (size_t)(crow + mt * 16) * N + ccol + nt * 8;
                float* p1 = p0 + 8 * (size_t)N;
                *(float2*)p0 = make_float2(acc[mt][nt][0], acc[mt][nt][1]);
                *(float2*)p1 = make_float2(acc[mt][nt][2], acc[mt][nt][3]);
            }
        }
    } else {
        // fused RoPE + fp16 hi/lo split. Warp tile = exactly one 64-dim head.
        const int hh = (n0 + wn * 64) >> 6;        // global head index 0..143
        const int g  = hh / 18, hd = hh % 18;
        const int crow = m0 + wm * 32 + (lane >> 2);
        const int d0base = (lane & 3) * 2;
        #pragma unroll
        for (int mt = 0; mt < 2; ++mt) {
            #pragma unroll
            for (int half = 0; half < 2; ++half) {
                const int r = crow + mt * 16 + half * 8;   // global token
                #pragma unroll
                for (int nt = 0; nt < 4; ++nt) {
                    const int d = d0base + nt * 8;          // 0..30 even
                    float x1a = acc[mt][nt][half * 2],     x1b = acc[mt][nt][half * 2 + 1];
                    float x2a = acc[mt][nt + 4][half * 2], x2b = acc[mt][nt + 4][half * 2 + 1];
                    float y1a, y1b, y2a, y2b;
                    if (hd < 17) {   // rope on q heads and k
                        float ca = cosv[r * 32 + d],  cb = cosv[r * 32 + d + 1];
                        float sa = sinv[r * 32 + d],  sb2 = sinv[r * 32 + d + 1];
                        y1a = x1a * ca - x2a * sa;  y2a = x2a * ca + x1a * sa;
                        y1b = x1b * cb - x2b * sb2; y2b = x2b * cb + x1b * sb2;
                    } else { y1a = x1a; y1b = x1b; y2a = x2a; y2b = x2b; }

                    uint32_t h1 = packh2(y1a, y1b);
                    uint32_t h2 = packh2(y2a, y2b);

                    if (hd < HQ) {
                        size_t off = (((size_t)r * GKV + g) * HQ + hd) * HEADD;
                        *(uint32_t*)(qh + off + d)      = h1;
                        *(uint32_t*)(ql + off + d)      = residh2(h1, y1a, y1b);
                        *(uint32_t*)(qh + off + d + 32) = h2;
                        *(uint32_t*)(ql + off + d + 32) = residh2(h2, y2a, y2b);
                    } else if (hd == HQ) {
                        size_t off = ((size_t)r * GKV + g) * HEADD;
                        *(uint32_t*)(kh + off + d)      = h1;
                        *(uint32_t*)(kl + off + d)      = residh2(h1, y1a, y1b);
                        *(uint32_t*)(kh + off + d + 32) = h2;
                        *(uint32_t*)(kl + off + d + 32) = residh2(h2, y2a, y2b);
                    } else {   // V: single fp16 only (PV is 1-pass)
                        size_t off = ((size_t)r * GKV + g) * HEADD;
                        *(uint32_t*)(vh + off + d)      = h1;
                        *(uint32_t*)(vh + off + d + 32) = h2;
                    }
                }
            }
        }
    }
    #undef ISSUE
}

// ---------------- HMMA flash attention ----------------
// QK^T: 3-pass split fp16 (precision-critical: logits). PV: 1-pass.
// KV stage = {Kh 8K | Kl 8K | Vh 8K} = 24 KB, 2 stages.
#define BQ 128
#define BKV 64
#define QSMB 32768
#define KVST 24576
#define ATT_SMEM (QSMB + 2 * KVST)

__global__ __launch_bounds__(256) void attn_mma_kernel(
    const h16* __restrict__ qh, const h16* __restrict__ ql,
    const h16* __restrict__ kh, const h16* __restrict__ kl,
    const h16* __restrict__ vh,
    h16* __restrict__ outo)
{
    extern __shared__ char smem[];
    const uint32_t sb = smem_u32(smem);
    const int qb = blockIdx.x;
    const int h  = blockIdx.y;
    const int bg = blockIdx.z;
    const int b  = bg >> 3, g = bg & 7;
    const int tid = threadIdx.x, wid = tid >> 5, lane = tid & 31;
    const int tb = b * SEQ, q0 = qb * BQ;

    const h16* kvsrc[3] = { kh, kl, vh };

    #pragma unroll
    for (int arr = 0; arr < 2; ++arr) {
        const h16* src = arr ? ql : qh;
        #pragma unroll
        for (int j = 0; j < 4; ++j) {
            const int i = tid + j * 256;
            const int r = i >> 3, ch = i & 7;
            const uint32_t dst = sb + arr * 16384 + SWZ((uint32_t)(r * 128 + ch * 16));
            const h16* gp = src + (((size_t)(tb + q0 + r) * GKV + g) * HQ + h) * HEADD + ch * 8;
            CPA16(dst, gp);
        }
    }
    CPA_COMMIT();

    #define ISSUE_KV(jb_, st_) do {                                                   \
        const int j0_ = (jb_) * BKV;                                                  \
        const uint32_t base_ = sb + QSMB + (st_) * KVST;                              \
        _Pragma("unroll")                                                             \
        for (int q_ = 0; q_ < 6; ++q_) {                                              \
            const int i_ = tid + q_ * 256;                                            \
            const int arr_ = i_ >> 9, r_ = (i_ >> 3) & 63, ch_ = i_ & 7;              \
            const h16* gp_ = kvsrc[arr_] + ((size_t)(tb + j0_ + r_) * GKV + g) * HEADD + ch_ * 8; \
            CPA16(base_ + arr_ * 8192 + SWZ((uint32_t)(r_ * 128 + ch_ * 16)), gp_);   \
        }                                                                             \
        CPA_COMMIT();                                                                 \
    } while (0)

    ISSUE_KV(0, 0);
    CPA_WAIT(1);
    __syncthreads();

    uint32_t aqh[4][4], aql[4][4];
    const int arow = wid * 16 + (lane & 15);
    const int ahalf = lane >> 4;
    #pragma unroll
    for (int ks = 0; ks < 4; ++ks) {
        ldmat_x4(aqh[ks], sb + SWZ((uint32_t)(arow * 128 + (ks * 2 + ahalf) * 16)));
        ldmat_x4(aql[ks], sb + 16384 + SWZ((uint32_t)(arow * 128 + (ks * 2 + ahalf) * 16)));
    }

    float acc[8][4];
    #pragma unroll
    for (int i = 0; i < 8; i++)
        #pragma unroll
        for (int q = 0; q < 4; q++) acc[i][q] = 0.f;
    float m0 = -1e30f, m1 = -1e30f, l0 = 0.f, l1 = 0.f;

    const int brow = ((lane >> 4) << 3) + (lane & 7);
    const int bhalf = (lane >> 3) & 1;
    const int jmax = 2 * qb + 1;

    for (int jb = 0; jb <= jmax; ++jb) {
        const int st = jb & 1;
        if (jb < jmax) { ISSUE_KV(jb + 1, (jb + 1) & 1); CPA_WAIT(1); }
        else           { CPA_WAIT(0); }
        __syncthreads();

        const uint32_t kbh = sb + QSMB + st * KVST;
        const uint32_t kbl = kbh + 8192;
        const uint32_t vbh = kbh + 16384;

        float s[8][4];
        #pragma unroll
        for (int i = 0; i < 8; i++)
            #pragma unroll
            for (int q = 0; q < 4; q++) s[i][q] = 0.f;

        #pragma unroll
        for (int ks = 0; ks < 4; ++ks) {
            #pragma unroll
            for (int g4 = 0; g4 < 4; ++g4) {
                uint32_t bb[4];
                ldmat_x4(bb, kbh + SWZ((uint32_t)((g4 * 16 + brow) * 128 + (ks * 2 + bhalf) * 16)));
                mma16816(s[2 * g4],     aqh[ks], &bb[0]);
                mma16816(s[2 * g4 + 1], aqh[ks], &bb[2]);
                mma16816(s[2 * g4],     aql[ks], &bb[0]);
                mma16816(s[2 * g4 + 1], aql[ks], &bb[2]);
                ldmat_x4(bb, kbl + SWZ((uint32_t)((g4 * 16 + brow) * 128 + (ks * 2 + bhalf) * 16)));
                mma16816(s[2 * g4],     aqh[ks], &bb[0]);
                mma16816(s[2 * g4 + 1], aqh[ks], &bb[2]);
            }
        }

        const float SCALE = 0.125f;
        const int j0 = jb * BKV;
        const int r0g = q0 + wid * 16 + (lane >> 2);
        if (jb >= 2 * qb) {
            #pragma unroll
            for (int nt = 0; nt < 8; ++nt) {
                const int kc = j0 + nt * 8 + (lane & 3) * 2;
                #pragma unroll
                for (int q = 0; q < 4; ++q) {
                    const int row = r0g + ((q >> 1) << 3);
                    const int key = kc + (q & 1);
                    s[nt][q] = (key <= row) ? s[nt][q] * SCALE : -1e30f;
                }
            }
        } else {
            #pragma unroll
            for (int nt = 0; nt < 8; ++nt)
                #pragma unroll
                for (int q = 0; q < 4; ++q) s[nt][q] *= SCALE;
        }

        float rm0 = -1e30f, rm1 = -1e30f;
        #pragma unroll
        for (int nt = 0; nt < 8; ++nt) {
            rm0 = fmaxf(rm0, fmaxf(s[nt][0], s[nt][1]));
            rm1 = fmaxf(rm1, fmaxf(s[nt][2], s[nt][3]));
        }
        rm0 = fmaxf(rm0, __shfl_xor_sync(0xffffffffu, rm0, 1));
        rm0 = fmaxf(rm0, __shfl_xor_sync(0xffffffffu, rm0, 2));
        rm1 = fmaxf(rm1, __shfl_xor_sync(0xffffffffu, rm1, 1));
        rm1 = fmaxf(rm1, __shfl_xor_sync(0xffffffffu, rm1, 2));

        const float nm0 = fmaxf(m0, rm0), nm1 = fmaxf(m1, rm1);
        const float c0 = __expf(m0 - nm0), c1 = __expf(m1 - nm1);
        float rs0 = 0.f, rs1 = 0.f;
        #pragma unroll
        for (int nt = 0; nt < 8; ++nt) {
            s[nt][0] = __expf(s[nt][0] - nm0);
            s[nt][1] = __expf(s[nt][1] - nm0);
            s[nt][2] = __expf(s[nt][2] - nm1);
            s[nt][3] = __expf(s[nt][3] - nm1);
            rs0 += s[nt][0] + s[nt][1];
            rs1 += s[nt][2] + s[nt][3];
        }
        rs0 += __shfl_xor_sync(0xffffffffu, rs0, 1);
        rs0 += __shfl_xor_sync(0xffffffffu, rs0, 2);
        rs1 += __shfl_xor_sync(0xffffffffu, rs1, 1);
        rs1 += __shfl_xor_sync(0xffffffffu, rs1, 2);
        l0 = l0 * c0 + rs0; l1 = l1 * c1 + rs1;
        m0 = nm0; m1 = nm1;
        #pragma unroll
        for (int nt = 0; nt < 8; ++nt) {
            acc[nt][0] *= c0; acc[nt][1] *= c0;
            acc[nt][2] *= c1; acc[nt][3] *= c1;
        }

        // P fragments: hi only (PV 1-pass)
        uint32_t ph[4][4];
        #pragma unroll
        for (int ks = 0; ks < 4; ++ks) {
            ph[ks][0] = packh2(s[2 * ks][0], s[2 * ks][1]);
            ph[ks][1] = packh2(s[2 * ks][2], s[2 * ks][3]);
            ph[ks][2] = packh2(s[2 * ks + 1][0], s[2 * ks + 1][1]);
            ph[ks][3] = packh2(s[2 * ks + 1][2], s[2 * ks + 1][3]);
        }

        const int vrow0 = ((lane >> 3) & 1) * 8 + (lane & 7);
        const int vch   = lane >> 4;
        #pragma unroll
        for (int ks = 0; ks < 4; ++ks) {
            #pragma unroll
            for (int g4 = 0; g4 < 4; ++g4) {
                uint32_t vv[4];
                ldmat_x4_t(vv, vbh + SWZ((uint32_t)((ks * 16 + vrow0) * 128 + (g4 * 2 + vch) * 16)));
                mma16816(acc[2 * g4],     ph[ks], &vv[0]);
                mma16816(acc[2 * g4 + 1], ph[ks], &vv[2]);
            }
        }
        __syncthreads();
    }
    #undef ISSUE_KV

    const float inv0 = 1.f / l0, inv1 = 1.f / l1;
    const int rA = q0 + wid * 16 + (lane >> 2);
    const size_t colbase = (size_t)(g * HQ + h) * HEADD + (lane & 3) * 2;
    #pragma unroll
    for (int half = 0; half < 2; ++half) {
        const int row = rA + half * 8;
        const float inv = half ? inv1 : inv0;
        const size_t base = (size_t)(tb + row) * HID + colbase;
        #pragma unroll
        for (int nt = 0; nt < 8; ++nt) {
            float v0 = acc[nt][half * 2] * inv;
            float v1 = acc[nt][half * 2 + 1] * inv;
            *(__half2*)(outo + base + nt * 8) = __floats2half2_rn(v0, v1);
        }
    }
}

// ---------------- launcher (single stream — serial; R13 overlap regressed) ----------------
extern "C" void kernel_launch(void* const* d_in, const int* in_sizes, int n_in,
                              void* d_out, int out_size)
{
    const float* hidden = (const float*)d_in[0];
    const float* cosv   = (const float*)d_in[1];
    const float* sinv   = (const float*)d_in[2];
    const float* Wqkv   = (const float*)d_in[3];
    const float* Wdense = (const float*)d_in[4];
    float* out = (float*)d_out;

    h16 *ahi, *alo, *oatt, *wqh, *wql, *wdh;
    h16 *qh, *ql, *kh, *kl, *vh;
    cudaGetSymbolAddress((void**)&ahi, g_ahi);
    cudaGetSymbolAddress((void**)&alo, g_alo);
    cudaGetSymbolAddress((void**)&oatt, g_o);
    cudaGetSymbolAddress((void**)&wqh, g_wq_hi);
    cudaGetSymbolAddress((void**)&wql, g_wq_lo);
    cudaGetSymbolAddress((void**)&wdh, g_wd_hi);
    cudaGetSymbolAddress((void**)&qh, g_qh);
    cudaGetSymbolAddress((void**)&ql, g_ql);
    cudaGetSymbolAddress((void**)&kh, g_kh);
    cudaGetSymbolAddress((void**)&kl, g_kl);
    cudaGetSymbolAddress((void**)&vh, g_vh);

    const int smem3 = NSTG * 4 * (128 * 64);    // 98304  (QKV: KC=32, 3-pass)
    const int smem1 = NSTG * 2 * (128 * 128);   // 98304  (dense: KC=64, 1-pass)
    cudaFuncSetAttribute(gemm_mma<3, 1, 32>, cudaFuncAttributeMaxDynamicSharedMemorySize, smem3);
    cudaFuncSetAttribute(gemm_mma<1, 0, 64>, cudaFuncAttributeMaxDynamicSharedMemorySize, smem1);
    cudaFuncSetAttribute(attn_mma_kernel, cudaFuncAttributeMaxDynamicSharedMemorySize, ATT_SMEM);

    // 0) operand conversions (serial — overlap attempt in R13 regressed)
    split_kernel<<<(T_TOK * HID / 4 + 255) / 256, 256>>>(hidden, ahi, alo, T_TOK * HID / 4);
    transpose_split_kernel<<<dim3(QKVW / 32, HID / 32), dim3(32, 8)>>>(Wqkv, HID, QKVW, wqh, wql);
    transpose_split_kernel<<<dim3(HID / 32, HID / 32), dim3(32, 8)>>>(Wdense, HID, HID, wdh, nullptr);

    // 1) QKV projection: 3-pass split fp16 with fused RoPE + split epilogue
    gemm_mma<3, 1, 32><<<dim3(QKVW / 128, T_TOK / 128), 256, smem3>>>(
        T_TOK, QKVW, HID, ahi, alo, wqh, wql, nullptr,
        cosv, sinv, qh, ql, kh, kl, vh);

    // 2) HMMA causal GQA flash attention (QK 3-pass, PV 1-pass) -> single fp16
    attn_mma_kernel<<<dim3(SEQ / BQ, HQ, 16), 256, ATT_SMEM>>>(
        qh, ql, kh, kl, vh, oatt);

    // 3) dense projection: single x single fp16, KC=64 (fewer barriers)
    gemm_mma<1, 0, 64><<<dim3(HID / 128, T_TOK / 128), 256, smem1>>>(
        T_TOK, HID, HID, oatt, nullptr, wdh, nullptr, out,
        nullptr, nullptr, nullptr, nullptr, nullptr, nullptr, nullptr);
}

// round 17
// speedup vs baseline: 1.5564x; 1.0197x over previous
#include <cuda_runtime.h>
#include <cuda_fp16.h>
#include <math.h>
#include <stdint.h>

// ---------------- problem constants ----------------
#define T_TOK 2048      // BATCH*SEQ
#define HID   8192
#define QKVW  9216      // G*(HQ+2)*HEAD = 8*18*64
#define GKV   8
#define HQ    16
#define HEADD 64
#define SEQ   1024

typedef __half h16;

// ---------------- scratch (__device__ globals; allocation-free rule) ----------------
__device__ __align__(128) h16  g_ahi[(size_t)T_TOK * HID];
__device__ __align__(128) h16  g_alo[(size_t)T_TOK * HID];
__device__ __align__(128) h16  g_o[(size_t)T_TOK * HID];          // attention out (single fp16)
__device__ __align__(128) h16  g_wq_hi[(size_t)QKVW * HID];
__device__ __align__(128) h16  g_wq_lo[(size_t)QKVW * HID];
__device__ __align__(128) h16  g_wd_hi[(size_t)HID * HID];
// split QKV for tensor-core attention (V needs no lo: PV is 1-pass)
__device__ __align__(128) h16  g_qh[(size_t)T_TOK * GKV * HQ * HEADD];
__device__ __align__(128) h16  g_ql[(size_t)T_TOK * GKV * HQ * HEADD];
__device__ __align__(128) h16  g_kh[(size_t)T_TOK * GKV * HEADD];
__device__ __align__(128) h16  g_kl[(size_t)T_TOK * GKV * HEADD];
__device__ __align__(128) h16  g_vh[(size_t)T_TOK * GKV * HEADD];

// ---------------- PTX helpers ----------------
__device__ __forceinline__ uint32_t smem_u32(const void* p) {
    uint32_t a;
    asm("{ .reg .u64 t; cvta.to.shared.u64 t, %1; cvt.u32.u64 %0, t; }" : "=r"(a) : "l"(p));
    return a;
}
#define CPA16(dst, src)   asm volatile("cp.async.cg.shared.global [%0], [%1], 16;" :: "r"(dst), "l"(src))
#define CPA_COMMIT()      asm volatile("cp.async.commit_group;" ::: "memory")
#define CPA_WAIT(n)       asm volatile("cp.async.wait_group %0;" :: "n"(n) : "memory")

__device__ __forceinline__ void ldmat_x4(uint32_t* r, uint32_t addr) {
    asm volatile("ldmatrix.sync.aligned.m8n8.x4.shared.b16 {%0,%1,%2,%3}, [%4];"
        : "=r"(r[0]), "=r"(r[1]), "=r"(r[2]), "=r"(r[3]) : "r"(addr));
}
__device__ __forceinline__ void ldmat_x4_t(uint32_t* r, uint32_t addr) {
    asm volatile("ldmatrix.sync.aligned.m8n8.x4.trans.shared.b16 {%0,%1,%2,%3}, [%4];"
        : "=r"(r[0]), "=r"(r[1]), "=r"(r[2]), "=r"(r[3]) : "r"(addr));
}
__device__ __forceinline__ void mma16816(float* d, const uint32_t* a, const uint32_t* b) {
    asm volatile("mma.sync.aligned.m16n8k16.row.col.f32.f16.f16.f32 "
        "{%0,%1,%2,%3}, {%4,%5,%6,%7}, {%8,%9}, {%0,%1,%2,%3};"
        : "+f"(d[0]), "+f"(d[1]), "+f"(d[2]), "+f"(d[3])
        : "r"(a[0]), "r"(a[1]), "r"(a[2]), "r"(a[3]), "r"(b[0]), "r"(b[1]));
}
#define SWZ(off)   ((off) ^ (((off) >> 3) & 0x70))   // 128B rows
#define SWZ64(off) ((off) ^ (((off) >> 3) & 0x30))   // 64B rows

__device__ __forceinline__ uint32_t gswz(uint32_t off, int rowb) {
    return (rowb == 64) ? SWZ64(off) : SWZ(off);
}

__device__ __forceinline__ uint32_t packh2(float a, float b) {
    __half2 t = __floats2half2_rn(a, b);
    return *(uint32_t*)&t;
}
__device__ __forceinline__ uint32_t residh2(uint32_t hp, float a, float b) {
    __half2 t = *(__half2*)&hp;
    return packh2(a - __half2float(t.x), b - __half2float(t.y));
}

// ---------------- fp32 -> (hi, lo) fp16 split ----------------
__global__ __launch_bounds__(256) void split_kernel(
    const float* __restrict__ x, h16* __restrict__ hi, h16* __restrict__ lo, int n4)
{
    int i = blockIdx.x * 256 + threadIdx.x;
    if (i >= n4) return;
    float4 v = *(const float4*)(x + (size_t)i * 4);
    __half2 h01 = __floats2half2_rn(v.x, v.y);
    __half2 h23 = __floats2half2_rn(v.z, v.w);
    __half2 l01 = __floats2half2_rn(v.x - __half2float(h01.x), v.y - __half2float(h01.y));
    __half2 l23 = __floats2half2_rn(v.z - __half2float(h23.x), v.w - __half2float(h23.y));
    *(__half2*)(hi + (size_t)i * 4)     = h01;
    *(__half2*)(hi + (size_t)i * 4 + 2) = h23;
    *(__half2*)(lo + (size_t)i * 4)     = l01;
    *(__half2*)(lo + (size_t)i * 4 + 2) = l23;
}

// ---------------- W [K,N] fp32 -> fp16 [N,K] transpose (+ optional lo split) ----------------
// Tile: 64 (k) x 32 (n). Writes pack 2 consecutive k-values per thread ->
// 128B fully-coalesced stores (the 32x32 version wrote 64B half-sectors).
__global__ __launch_bounds__(256) void transpose_split_kernel(
    const float* __restrict__ W, int K, int N, h16* __restrict__ oh, h16* __restrict__ ol)
{
    __shared__ float t[64][33];
    const int tx = threadIdx.x, ty = threadIdx.y;     // block (32, 8)
    const int k0 = blockIdx.y * 64, n0 = blockIdx.x * 32;
    #pragma unroll
    for (int j = ty; j < 64; j += 8)
        t[j][tx] = W[(size_t)(k0 + j) * N + n0 + tx];
    __syncthreads();
    #pragma unroll
    for (int j = ty; j < 32; j += 8) {
        float v0 = t[2 * tx][j];
        float v1 = t[2 * tx + 1][j];
        uint32_t hpk = packh2(v0, v1);
        *(uint32_t*)(oh + (size_t)(n0 + j) * K + k0 + 2 * tx) = hpk;
        if (ol)
            *(uint32_t*)(ol + (size_t)(n0 + j) * K + k0 + 2 * tx) = residh2(hpk, v0, v1);
    }
}

// ---------------- split-fp16 GEMM via mma.sync ----------------
// CTA tile 128x128, 8 warps (4M x 2N), 3-stage cp.async, one barrier/chunk.
//   QKV:   PASSES=3, KCHUNK=64, MINB=1 (stage 64 KB x 3 = 192 KB; R8-validated best)
//   dense: PASSES=1, KCHUNK=64, MINB=2 (stage 32 KB x 3 = 96 KB; 2 CTAs/SM)
// EPI==0: fp32 C.  EPI==1: fused RoPE + fp16 hi/lo split to q/k/v arrays.
#define NSTG 3

template<int PASSES, int EPI, int KCHUNK, int MINB>
__global__ __launch_bounds__(256, MINB) void gemm_mma(
    int M, int N, int K,
    const h16* __restrict__ A0, const h16* __restrict__ A1,
    const h16* __restrict__ B0, const h16* __restrict__ B1,
    float* __restrict__ C,
    const float* __restrict__ cosv, const float* __restrict__ sinv,
    h16* __restrict__ qh, h16* __restrict__ ql,
    h16* __restrict__ kh, h16* __restrict__ kl,
    h16* __restrict__ vh)
{
    constexpr int NTILE = (PASSES == 3) ? 4 : 2;
    constexpr int ROWB  = KCHUNK * 2;          // bytes per tile row
    constexpr int NKS   = KCHUNK / 16;         // k-steps per chunk
    constexpr int CPR   = ROWB / 16;           // 16B chunks per row
    constexpr uint32_t TB = 128u * ROWB;       // tile bytes
    constexpr uint32_t SB = NTILE * TB;        // stage bytes
    constexpr int CHT = NTILE * 128 * CPR / 256;  // per-thread cp.async per stage

    extern __shared__ char smem[];
    const uint32_t sb = smem_u32(smem);
    const int tid = threadIdx.x, wid = tid >> 5, lane = tid & 31;
    const int m0 = blockIdx.y * 128, n0 = blockIdx.x * 128;
    const int wm = wid & 3, wn = wid >> 2;

    const h16* srcs4[4] = { A0, A1, B0, B1 };
    const h16* srcs2[2] = { A0, B0 };
    const int rb4[4] = { m0, m0, n0, n0 };
    const int rb2[2] = { m0, n0 };

    float acc[2][8][4];
    #pragma unroll
    for (int i = 0; i < 2; i++)
        #pragma unroll
        for (int j = 0; j < 8; j++)
            #pragma unroll
            for (int q = 0; q < 4; q++) acc[i][j][q] = 0.f;

    const int nch = K / KCHUNK;

    #define ISSUE(c, st) do {                                                     \
        const uint32_t base_ = sb + (uint32_t)(st) * SB;                          \
        _Pragma("unroll")                                                         \
        for (int j_ = 0; j_ < CHT; ++j_) {                                        \
            const int i_ = tid + j_ * 256;                                        \
            const int t_ = i_ / (128 * CPR);                                      \
            const int rem_ = i_ - t_ * 128 * CPR;                                 \
            const int r_ = rem_ / CPR, ch_ = rem_ % CPR;                          \
            const uint32_t dst_ = base_ + t_ * TB + gswz((uint32_t)(r_ * ROWB + ch_ * 16), ROWB); \
            const h16* g_ = (PASSES == 3 ? srcs4[t_] : srcs2[t_])                 \
                + (size_t)((PASSES == 3 ? rb4[t_] : rb2[t_]) + r_) * K + (c) * KCHUNK + ch_ * 8; \
            CPA16(dst_, g_);                                                      \
        }                                                                         \
        CPA_COMMIT();                                                             \
    } while (0)

    ISSUE(0, 0);
    if (nch > 1) ISSUE(1, 1);

    const int arow = wm * 32 + (lane & 15);
    const int ahalf = lane >> 4;
    const int brow = wn * 64 + ((lane >> 4) << 3) + (lane & 7);
    const int bhalf = (lane >> 3) & 1;

    for (int c = 0; c < nch; ++c) {
        if (c + 1 < nch) { CPA_WAIT(1); } else { CPA_WAIT(0); }
        __syncthreads();
        if (c + 2 < nch) ISSUE(c + 2, (c + 2) % NSTG);

        const uint32_t base = sb + (uint32_t)(c % NSTG) * SB;
        const uint32_t abh = base;
        const uint32_t abl = base + TB;                           // PASSES==3 only
        const uint32_t bbh = base + ((PASSES == 3) ? 2 * TB : TB);
        const uint32_t bbl = bbh + TB;                            // PASSES==3 only

        #pragma unroll
        for (int ks = 0; ks < NKS; ++ks) {
            uint32_t ah[2][4], al[2][4], bh[4][4], bl[4][4];
            #pragma unroll
            for (int mt = 0; mt < 2; ++mt) {
                ldmat_x4(ah[mt], abh + gswz((uint32_t)((arow + mt * 16) * ROWB + (ks * 2 + ahalf) * 16), ROWB));
                if (PASSES == 3)
                    ldmat_x4(al[mt], abl + gswz((uint32_t)((arow + mt * 16) * ROWB + (ks * 2 + ahalf) * 16), ROWB));
            }
            #pragma unroll
            for (int n4 = 0; n4 < 4; ++n4) {
                ldmat_x4(bh[n4], bbh + gswz((uint32_t)((brow + n4 * 16) * ROWB + (ks * 2 + bhalf) * 16), ROWB));
                if (PASSES == 3)
                    ldmat_x4(bl[n4], bbl + gswz((uint32_t)((brow + n4 * 16) * ROWB + (ks * 2 + bhalf) * 16), ROWB));
            }
            #pragma unroll
            for (int mt = 0; mt < 2; ++mt)
                #pragma unroll
                for (int nt = 0; nt < 8; ++nt)
                    mma16816(acc[mt][nt], ah[mt], &bh[nt >> 1][(nt & 1) * 2]);
            if (PASSES == 3) {
                #pragma unroll
                for (int mt = 0; mt < 2; ++mt)
                    #pragma unroll
                    for (int nt = 0; nt < 8; ++nt)
                        mma16816(acc[mt][nt], ah[mt], &bl[nt >> 1][(nt & 1) * 2]);
                #pragma unroll
                for (int mt = 0; mt < 2; ++mt)
                    #pragma unroll
                    for (int nt = 0; nt < 8; ++nt)
                        mma16816(acc[mt][nt], al[mt], &bh[nt >> 1][(nt & 1) * 2]);
            }
        }
    }

    if (EPI == 0) {
        const int crow = m0 + wm * 32 + (lane >> 2);
        const int ccol = n0 + wn * 64 + (lane & 3) * 2;
        #pragma unroll
        for (int mt = 0; mt < 2; ++mt) {
            #pragma unroll
            for (int nt = 0; nt < 8; ++nt) {
                float* p0 = C + (size_t)(crow + mt * 16) * N + ccol + nt * 8;
                float* p1 = p0 + 8 * (size_t)N;
                *(float2*)p0 = make_float2(acc[mt][nt][0], acc[mt][nt][1]);
                *(float2*)p1 = make_float2(acc[mt][nt][2], acc[mt][nt][3]);
            }
        }
    } else {
        // fused RoPE + fp16 hi/lo split. Warp tile = exactly one 64-dim head.
        const int hh = (n0 + wn * 64) >> 6;        // global head index 0..143
        const int g  = hh / 18, hd = hh % 18;
        const int crow = m0 + wm * 32 + (lane >> 2);
        const int d0base = (lane & 3) * 2;
        #pragma unroll
        for (int mt = 0; mt < 2; ++mt) {
            #pragma unroll
            for (int half = 0; half < 2; ++half) {
                const int r = crow + mt * 16 + half * 8;   // global token
                #pragma unroll
                for (int nt = 0; nt < 4; ++nt) {
                    const int d = d0base + nt * 8;          // 0..30 even
                    float x1a = acc[mt][nt][half * 2],     x1b = acc[mt][nt][half * 2 + 1];
                    float x2a = acc[mt][nt + 4][half * 2], x2b = acc[mt][nt + 4][half * 2 + 1];
                    float y1a, y1b, y2a, y2b;
                    if (hd < 17) {   // rope on q heads and k
                        float ca = cosv[r * 32 + d],  cb = cosv[r * 32 + d + 1];
                        float sa = sinv[r * 32 + d],  sb2 = sinv[r * 32 + d + 1];
                        y1a = x1a * ca - x2a * sa;  y2a = x2a * ca + x1a * sa;
                        y1b = x1b * cb - x2b * sb2; y2b = x2b * cb + x1b * sb2;
                    } else { y1a = x1a; y1b = x1b; y2a = x2a; y2b = x2b; }

                    uint32_t h1 = packh2(y1a, y1b);
                    uint32_t h2 = packh2(y2a, y2b);

                    if (hd < HQ) {
                        size_t off = (((size_t)r * GKV + g) * HQ + hd) * HEADD;
                        *(uint32_t*)(qh + off + d)      = h1;
                        *(uint32_t*)(ql + off + d)      = residh2(h1, y1a, y1b);
                        *(uint32_t*)(qh + off + d + 32) = h2;
                        *(uint32_t*)(ql + off + d + 32) = residh2(h2, y2a, y2b);
                    } else if (hd == HQ) {
                        size_t off = ((size_t)r * GKV + g) * HEADD;
                        *(uint32_t*)(kh + off + d)      = h1;
                        *(uint32_t*)(kl + off + d)      = residh2(h1, y1a, y1b);
                        *(uint32_t*)(kh + off + d + 32) = h2;
                        *(uint32_t*)(kl + off + d + 32) = residh2(h2, y2a, y2b);
                    } else {   // V: single fp16 only (PV is 1-pass)
                        size_t off = ((size_t)r * GKV + g) * HEADD;
                        *(uint32_t*)(vh + off + d)      = h1;
                        *(uint32_t*)(vh + off + d + 32) = h2;
                    }
                }
            }
        }
    }
    #undef ISSUE
}

// ---------------- HMMA flash attention ----------------
// QK^T: 3-pass split fp16 (precision-critical: logits). PV: 1-pass.
// KV stage = {Kh 8K | Kl 8K | Vh 8K} = 24 KB, 2 stages.
#define BQ 128
#define BKV 64
#define QSMB 32768
#define KVST 24576
#define ATT_SMEM (QSMB + 2 * KVST)

__global__ __launch_bounds__(256) void attn_mma_kernel(
    const h16* __restrict__ qh, const h16* __restrict__ ql,
    const h16* __restrict__ kh, const h16* __restrict__ kl,
    const h16* __restrict__ vh,
    h16* __restrict__ outo)
{
    extern __shared__ char smem[];
    const uint32_t sb = smem_u32(smem);
    const int qb = blockIdx.x;
    const int h  = blockIdx.y;
    const int bg = blockIdx.z;
    const int b  = bg >> 3, g = bg & 7;
    const int tid = threadIdx.x, wid = tid >> 5, lane = tid & 31;
    const int tb = b * SEQ, q0 = qb * BQ;

    const h16* kvsrc[3] = { kh, kl, vh };

    #pragma unroll
    for (int arr = 0; arr < 2; ++arr) {
        const h16* src = arr ? ql : qh;
        #pragma unroll
        for (int j = 0; j < 4; ++j) {
            const int i = tid + j * 256;
            const int r = i >> 3, ch = i & 7;
            const uint32_t dst = sb + arr * 16384 + SWZ((uint32_t)(r * 128 + ch * 16));
            const h16* gp = src + (((size_t)(tb + q0 + r) * GKV + g) * HQ + h) * HEADD + ch * 8;
            CPA16(dst, gp);
        }
    }
    CPA_COMMIT();

    #define ISSUE_KV(jb_, st_) do {                                                   \
        const int j0_ = (jb_) * BKV;                                                  \
        const uint32_t base_ = sb + QSMB + (st_) * KVST;                              \
        _Pragma("unroll")                                                             \
        for (int q_ = 0; q_ < 6; ++q_) {                                              \
            const int i_ = tid + q_ * 256;                                            \
            const int arr_ = i_ >> 9, r_ = (i_ >> 3) & 63, ch_ = i_ & 7;              \
            const h16* gp_ = kvsrc[arr_] + ((size_t)(tb + j0_ + r_) * GKV + g) * HEADD + ch_ * 8; \
            CPA16(base_ + arr_ * 8192 + SWZ((uint32_t)(r_ * 128 + ch_ * 16)), gp_);   \
        }                                                                             \
        CPA_COMMIT();                                                                 \
    } while (0)

    ISSUE_KV(0, 0);
    CPA_WAIT(1);
    __syncthreads();

    uint32_t aqh[4][4], aql[4][4];
    const int arow = wid * 16 + (lane & 15);
    const int ahalf = lane >> 4;
    #pragma unroll
    for (int ks = 0; ks < 4; ++ks) {
        ldmat_x4(aqh[ks], sb + SWZ((uint32_t)(arow * 128 + (ks * 2 + ahalf) * 16)));
        ldmat_x4(aql[ks], sb + 16384 + SWZ((uint32_t)(arow * 128 + (ks * 2 + ahalf) * 16)));
    }

    float acc[8][4];
    #pragma unroll
    for (int i = 0; i < 8; i++)
        #pragma unroll
        for (int q = 0; q < 4; q++) acc[i][q] = 0.f;
    float m0 = -1e30f, m1 = -1e30f, l0 = 0.f, l1 = 0.f;

    const int brow = ((lane >> 4) << 3) + (lane & 7);
    const int bhalf = (lane >> 3) & 1;
    const int jmax = 2 * qb + 1;

    for (int jb = 0; jb <= jmax; ++jb) {
        const int st = jb & 1;
        if (jb < jmax) { ISSUE_KV(jb + 1, (jb + 1) & 1); CPA_WAIT(1); }
        else           { CPA_WAIT(0); }
        __syncthreads();

        const uint32_t kbh = sb + QSMB + st * KVST;
        const uint32_t kbl = kbh + 8192;
        const uint32_t vbh = kbh + 16384;

        float s[8][4];
        #pragma unroll
        for (int i = 0; i < 8; i++)
            #pragma unroll
            for (int q = 0; q < 4; q++) s[i][q] = 0.f;

        #pragma unroll
        for (int ks = 0; ks < 4; ++ks) {
            #pragma unroll
            for (int g4 = 0; g4 < 4; ++g4) {
                uint32_t bb[4];
                ldmat_x4(bb, kbh + SWZ((uint32_t)((g4 * 16 + brow) * 128 + (ks * 2 + bhalf) * 16)));
                mma16816(s[2 * g4],     aqh[ks], &bb[0]);
                mma16816(s[2 * g4 + 1], aqh[ks], &bb[2]);
                mma16816(s[2 * g4],     aql[ks], &bb[0]);
                mma16816(s[2 * g4 + 1], aql[ks], &bb[2]);
                ldmat_x4(bb, kbl + SWZ((uint32_t)((g4 * 16 + brow) * 128 + (ks * 2 + bhalf) * 16)));
                mma16816(s[2 * g4],     aqh[ks], &bb[0]);
                mma16816(s[2 * g4 + 1], aqh[ks], &bb[2]);
            }
        }

        const float SCALE = 0.125f;
        const int j0 = jb * BKV;
        const int r0g = q0 + wid * 16 + (lane >> 2);
        if (jb >= 2 * qb) {
            #pragma unroll
            for (int nt = 0; nt < 8; ++nt) {
                const int kc = j0 + nt * 8 + (lane & 3) * 2;
                #pragma unroll
                for (int q = 0; q < 4; ++q) {
                    const int row = r0g + ((q >> 1) << 3);
                    const int key = kc + (q & 1);
                    s[nt][q] = (key <= row) ? s[nt][q] * SCALE : -1e30f;
                }
            }
        } else {
            #pragma unroll
            for (int nt = 0; nt < 8; ++nt)
                #pragma unroll
                for (int q = 0; q < 4; ++q) s[nt][q] *= SCALE;
        }

        float rm0 = -1e30f, rm1 = -1e30f;
        #pragma unroll
        for (int nt = 0; nt < 8; ++nt) {
            rm0 = fmaxf(rm0, fmaxf(s[nt][0], s[nt][1]));
            rm1 = fmaxf(rm1, fmaxf(s[nt][2], s[nt][3]));
        }
        rm0 = fmaxf(rm0, __shfl_xor_sync(0xffffffffu, rm0, 1));
        rm0 = fmaxf(rm0, __shfl_xor_sync(0xffffffffu, rm0, 2));
        rm1 = fmaxf(rm1, __shfl_xor_sync(0xffffffffu, rm1, 1));
        rm1 = fmaxf(rm1, __shfl_xor_sync(0xffffffffu, rm1, 2));

        const float nm0 = fmaxf(m0, rm0), nm1 = fmaxf(m1, rm1);
        const float c0 = __expf(m0 - nm0), c1 = __expf(m1 - nm1);
        float rs0 = 0.f, rs1 = 0.f;
        #pragma unroll
        for (int nt = 0; nt < 8; ++nt) {
            s[nt][0] = __expf(s[nt][0] - nm0);
            s[nt][1] = __expf(s[nt][1] - nm0);
            s[nt][2] = __expf(s[nt][2] - nm1);
            s[nt][3] = __expf(s[nt][3] - nm1);
            rs0 += s[nt][0] + s[nt][1];
            rs1 += s[nt][2] + s[nt][3];
        }
        rs0 += __shfl_xor_sync(0xffffffffu, rs0, 1);
        rs0 += __shfl_xor_sync(0xffffffffu, rs0, 2);
        rs1 += __shfl_xor_sync(0xffffffffu, rs1, 1);
        rs1 += __shfl_xor_sync(0xffffffffu, rs1, 2);
        l0 = l0 * c0 + rs0; l1 = l1 * c1 + rs1;
        m0 = nm0; m1 = nm1;
        #pragma unroll
        for (int nt = 0; nt < 8; ++nt) {
            acc[nt][0] *= c0; acc[nt][1] *= c0;
            acc[nt][2] *= c1; acc[nt][3] *= c1;
        }

        // P fragments: hi only (PV 1-pass)
        uint32_t ph[4][4];
        #pragma unroll
        for (int ks = 0; ks < 4; ++ks) {
            ph[ks][0] = packh2(s[2 * ks][0], s[2 * ks][1]);
            ph[ks][1] = packh2(s[2 * ks][2], s[2 * ks][3]);
            ph[ks][2] = packh2(s[2 * ks + 1][0], s[2 * ks + 1][1]);
            ph[ks][3] = packh2(s[2 * ks + 1][2], s[2 * ks + 1][3]);
        }

        const int vrow0 = ((lane >> 3) & 1) * 8 + (lane & 7);
        const int vch   = lane >> 4;
        #pragma unroll
        for (int ks = 0; ks < 4; ++ks) {
            #pragma unroll
            for (int g4 = 0; g4 < 4; ++g4) {
                uint32_t vv[4];
                ldmat_x4_t(vv, vbh + SWZ((uint32_t)((ks * 16 + vrow0) * 128 + (g4 * 2 + vch) * 16)));
                mma16816(acc[2 * g4],     ph[ks], &vv[0]);
                mma16816(acc[2 * g4 + 1], ph[ks], &vv[2]);
            }
        }
        __syncthreads();
    }
    #undef ISSUE_KV

    const float inv0 = 1.f / l0, inv1 = 1.f / l1;
    const int rA = q0 + wid * 16 + (lane >> 2);
    const size_t colbase = (size_t)(g * HQ + h) * HEADD + (lane & 3) * 2;
    #pragma unroll
    for (int half = 0; half < 2; ++half) {
        const int row = rA + half * 8;
        const float inv = half ? inv1 : inv0;
        const size_t base = (size_t)(tb + row) * HID + colbase;
        #pragma unroll
        for (int nt = 0; nt < 8; ++nt) {
            float v0 = acc[nt][half * 2] * inv;
            float v1 = acc[nt][half * 2 + 1] * inv;
            *(__half2*)(outo + base + nt * 8) = __floats2half2_rn(v0, v1);
        }
    }
}

// ---------------- launcher (single stream, serial) ----------------
extern "C" void kernel_launch(void* const* d_in, const int* in_sizes, int n_in,
                              void* d_out, int out_size)
{
    const float* hidden = (const float*)d_in[0];
    const float* cosv   = (const float*)d_in[1];
    const float* sinv   = (const float*)d_in[2];
    const float* Wqkv   = (const float*)d_in[3];
    const float* Wdense = (const float*)d_in[4];
    float* out = (float*)d_out;

    h16 *ahi, *alo, *oatt, *wqh, *wql, *wdh;
    h16 *qh, *ql, *kh, *kl, *vh;
    cudaGetSymbolAddress((void**)&ahi, g_ahi);
    cudaGetSymbolAddress((void**)&alo, g_alo);
    cudaGetSymbolAddress((void**)&oatt, g_o);
    cudaGetSymbolAddress((void**)&wqh, g_wq_hi);
    cudaGetSymbolAddress((void**)&wql, g_wq_lo);
    cudaGetSymbolAddress((void**)&wdh, g_wd_hi);
    cudaGetSymbolAddress((void**)&qh, g_qh);
    cudaGetSymbolAddress((void**)&ql, g_ql);
    cudaGetSymbolAddress((void**)&kh, g_kh);
    cudaGetSymbolAddress((void**)&kl, g_kl);
    cudaGetSymbolAddress((void**)&vh, g_vh);

    const int smem3 = NSTG * 4 * (128 * 128);   // 196608 (QKV: KC=64, 3-pass, 1 CTA/SM)
    const int smem1 = NSTG * 2 * (128 * 128);   // 98304  (dense: KC=64, 1-pass, 2 CTAs/SM)
    cudaFuncSetAttribute(gemm_mma<3, 1, 64, 1>, cudaFuncAttributeMaxDynamicSharedMemorySize, smem3);
    cudaFuncSetAttribute(gemm_mma<1, 0, 64, 2>, cudaFuncAttributeMaxDynamicSharedMemorySize, smem1);
    cudaFuncSetAttribute(attn_mma_kernel, cudaFuncAttributeMaxDynamicSharedMemorySize, ATT_SMEM);

    // 0) operand conversions (serial; R13 showed stream overlap regresses)
    split_kernel<<<(T_TOK * HID / 4 + 255) / 256, 256>>>(hidden, ahi, alo, T_TOK * HID / 4);
    transpose_split_kernel<<<dim3(QKVW / 32, HID / 64), dim3(32, 8)>>>(Wqkv, HID, QKVW, wqh, wql);
    transpose_split_kernel<<<dim3(HID / 32, HID / 64), dim3(32, 8)>>>(Wdense, HID, HID, wdh, nullptr);

    // 1) QKV projection: 3-pass split fp16, KC=64 (R8 best config), fused RoPE epilogue
    gemm_mma<3, 1, 64, 1><<<dim3(QKVW / 128, T_TOK / 128), 256, smem3>>>(
        T_TOK, QKVW, HID, ahi, alo, wqh, wql, nullptr,
        cosv, sinv, qh, ql, kh, kl, vh);

    // 2) HMMA causal GQA flash attention (QK 3-pass, PV 1-pass) -> single fp16
    attn_mma_kernel<<<dim3(SEQ / BQ, HQ, 16), 256, ATT_SMEM>>>(
        qh, ql, kh, kl, vh, oatt);

    // 3) dense projection: single x single fp16, KC=64, 2 CTAs/SM
    gemm_mma<1, 0, 64, 2><<<dim3(HID / 128, T_TOK / 128), 256, smem1>>>(
        T_TOK, HID, HID, oatt, nullptr, wdh, nullptr, out,
        nullptr, nullptr, nullptr, nullptr, nullptr, nullptr, nullptr);
}